// round 6
// baseline (speedup 1.0000x reference)
#include <cuda_runtime.h>

#define W_ 256
#define H_ 256
#define HW_ 65536
#define B_ 4
#define C_ 256
#define R_ 32
#define K_ 6

// 32 MB scratch for conf0 (B,R,H,W) — __device__ global (no allocation).
__device__ float g_conf0[B_ * R_ * HW_];
// f32 sin/cos of the 32 ray angles via libdevice sinf/cosf (== XLA:GPU lowering).
__device__ float g_sin[R_];
__device__ float g_cos[R_];

__constant__ float c_ef[5] = {0.2f, 0.4f, 0.6f, 0.8f, 1.0f};

__global__ void init_trig_kernel()
{
    int r = threadIdx.x;
    if (r < R_) {
        // ang = fl32( fl32(r/32) * fl32(2*pi) ) — exact f32 chain of the reference
        float ang = __fmul_rn(__fdiv_rn((float)r, 32.0f), 6.28318530717958647692f);
        g_sin[r] = sinf(ang);   // libdevice __nv_sinf
        g_cos[r] = cosf(ang);   // libdevice __nv_cosf
    }
}

// Kernel 1: conf0[b,r,h,w] = sum_c features[b,c,h,w] * w0[r,c]  (fp32, fma)
__global__ __launch_bounds__(256) void conf0_kernel(
    const float* __restrict__ features,
    const float* __restrict__ w0)
{
    __shared__ float w0s[C_ * R_];  // [c][r]
    for (int i = threadIdx.x; i < C_ * R_; i += blockDim.x) {
        int r = i & (R_ - 1);
        int c = i >> 5;
        w0s[i] = w0[r * C_ + c];
    }
    __syncthreads();

    int gp  = blockIdx.x * blockDim.x + threadIdx.x;  // pixel among B*HW
    int b   = gp >> 16;
    int pix = gp & (HW_ - 1);

    const float* fbase = features + (size_t)b * C_ * HW_ + pix;

    float acc[R_];
#pragma unroll
    for (int r = 0; r < R_; r++) acc[r] = 0.0f;

#pragma unroll 4
    for (int c = 0; c < C_; c++) {
        float f = __ldg(fbase + (size_t)c * HW_);
#pragma unroll
        for (int r = 0; r < R_; r++)
            acc[r] = fmaf(f, w0s[c * R_ + r], acc[r]);
    }

    float* obase = g_conf0 + (size_t)b * R_ * HW_ + pix;
#pragma unroll
    for (int r = 0; r < R_; r++)
        obase[(size_t)r * HW_] = acc[r];
}

// Kernel 2: fused erosion sampling + 6x6 matvec + bias + softmax + weighted sum + ReLU
__global__ __launch_bounds__(256) void refine_kernel(
    const float* __restrict__ sd,       // stardist (B,R,H,W)
    const float* __restrict__ w1,       // (K,K)
    const float* __restrict__ b1,       // (K,)
    float* __restrict__ ray_out,        // (B,R,H,W)
    float* __restrict__ conf_out)       // (B,K,R,H,W)
{
    __shared__ float w1s[K_ * K_];
    __shared__ float b1s[K_];
    if (threadIdx.x < K_ * K_) w1s[threadIdx.x] = w1[threadIdx.x];
    if (threadIdx.x < K_)      b1s[threadIdx.x] = b1[threadIdx.x];
    __syncthreads();

    int t = blockIdx.x * blockDim.x + threadIdx.x;  // < 2^23, fits int
    int w = t & (W_ - 1);
    int h = (t >> 8) & (H_ - 1);
    int r = (t >> 16) & (R_ - 1);

    float s  = sd[t];
    float c0 = g_conf0[t];

    float sn = g_sin[r];
    float cs = g_cos[r];

    int plane = t & ~(HW_ - 1);  // base of the (b,r) plane
    const float* plane_s = sd + plane;
    const float* plane_c = g_conf0 + plane;

    float rays[K_], confs[K_];
    rays[0]  = s;
    confs[0] = c0;

    const float wf = (float)w;
    const float hf = (float)h;

    // XLA canonicalizes x / const -> x * fl(1/const). Nearest f32 to 1/255,
    // folded at compile time with round-to-nearest (bits 0x3B808081).
    const float INV255 = 1.0f / 255.0f;

    // Index chain: separate IEEE single ops (no FMA contraction), division
    // replaced by reciprocal-constant multiply to match XLA's simplifier.
#pragma unroll
    for (int e = 0; e < 5; e++) {
        float ef   = c_ef[e];
        float base = __fmul_rn(__fadd_rn(s, -1.0f), ef);
        float gx   = __fadd_rn(wf, __fmul_rn(cs, base));
        float gy   = __fadd_rn(hf, __fmul_rn(sn, base));
        float nx   = __fadd_rn(__fmul_rn(__fmul_rn(gx, INV255), 2.0f), -1.0f);
        float ny   = __fadd_rn(__fmul_rn(__fmul_rn(gy, INV255), 2.0f), -1.0f);
        float ixf  = __fmul_rn(__fadd_rn(__fmul_rn(__fadd_rn(nx, 1.0f), 256.0f), -1.0f), 0.5f);
        float iyf  = __fmul_rn(__fadd_rn(__fmul_rn(__fadd_rn(ny, 1.0f), 256.0f), -1.0f), 0.5f);
        float ixr  = rintf(ixf);  // round half to even == jnp.round
        float iyr  = rintf(iyf);
        bool valid = (ixr >= 0.0f) && (ixr < 256.0f) && (iyr >= 0.0f) && (iyr < 256.0f);
        int ix = min(max((int)ixr, 0), W_ - 1);
        int iy = min(max((int)iyr, 0), H_ - 1);
        int gi = iy * W_ + ix;
        float ss = valid ? plane_s[gi] : 0.0f;
        float cc = valid ? plane_c[gi] : 0.0f;
        rays[e + 1]  = __fadd_rn(ss, base);
        confs[e + 1] = cc;
    }

    // z[j] = sum_k w1[j,k]*confs[k] + b1[j]; softmax over j
    float z[K_];
    float m = -3.0e38f;
#pragma unroll
    for (int j = 0; j < K_; j++) {
        float zz = 0.0f;
#pragma unroll
        for (int k = 0; k < K_; k++)
            zz = fmaf(w1s[j * K_ + k], confs[k], zz);
        zz = __fadd_rn(zz, b1s[j]);
        z[j] = zz;
        m = fmaxf(m, zz);
    }
    float sum = 0.0f;
#pragma unroll
    for (int j = 0; j < K_; j++) {
        z[j] = expf(__fadd_rn(z[j], -m));
        sum = __fadd_rn(sum, z[j]);
    }

    int hw = t & (HW_ - 1);
    size_t out_base = ((size_t)((t >> 21) * K_ * R_ + r)) * HW_ + hw;

    float acc = 0.0f;
#pragma unroll
    for (int j = 0; j < K_; j++) {
        float cf = __fdiv_rn(z[j], sum);
        acc = __fadd_rn(acc, __fmul_rn(rays[j], cf));
        conf_out[out_base + (size_t)(j * R_) * HW_] = cf;
    }
    ray_out[t] = fmaxf(acc, 0.0f);
}

extern "C" void kernel_launch(void* const* d_in, const int* in_sizes, int n_in,
                              void* d_out, int out_size)
{
    const float* sd       = (const float*)d_in[0];  // stardist_map (B,R,H,W)
    const float* features = (const float*)d_in[1];  // (B,C,H,W)
    const float* w0       = (const float*)d_in[2];  // (R,C)
    const float* w1       = (const float*)d_in[3];  // (K,K)
    const float* b1       = (const float*)d_in[4];  // (K,)

    float* out      = (float*)d_out;
    float* ray_out  = out;                              // (B,R,H,W)
    float* conf_out = out + (size_t)B_ * R_ * HW_;      // (B,K,R,H,W)

    init_trig_kernel<<<1, 32>>>();
    conf0_kernel<<<(B_ * HW_) / 256, 256>>>(features, w0);
    refine_kernel<<<(B_ * R_ * HW_) / 256, 256>>>(sd, w1, b1, ray_out, conf_out);
}